// round 1
// baseline (speedup 1.0000x reference)
#include <cuda_runtime.h>
#include <cuda_bf16.h>

#define BB 32
#define TT 1024
#define HH 384
#define MM 4096
#define PACE 1.0f
#define H4 (HH/4)          // 96 float4 per row
#define FPB 96             // frames per block

__device__ int g_csum[BB * TT];
__device__ int g_declen[BB];

// ---------------------------------------------------------------------------
// Kernel 1: per-batch inclusive scan of reps, dec_lens, tail write
// ---------------------------------------------------------------------------
__global__ void scan_kernel(const int* __restrict__ dur,
                            float* __restrict__ out_tail /* may be null */)
{
    __shared__ int s[TT];
    const int b = blockIdx.x;
    const int t = threadIdx.x;

    int v = (int)rintf((float)dur[b * TT + t] / PACE);
    s[t] = v;
    __syncthreads();
#pragma unroll
    for (int off = 1; off < TT; off <<= 1) {
        int add = (t >= off) ? s[t - off] : 0;
        __syncthreads();
        s[t] += add;
        __syncthreads();
    }
    g_csum[b * TT + t] = s[t];
    if (t == TT - 1) {
        int dl = min(s[t], MM);
        g_declen[b] = dl;
        if (out_tail) out_tail[b] = (float)dl;
    }
}

// ---------------------------------------------------------------------------
// Kernel 2: fused pitch/energy conv + length regulation (gather)
// Each thread owns 4 consecutive H-channels; conv weights live in registers.
// ---------------------------------------------------------------------------
__global__ __launch_bounds__(FPB)
void regulate_kernel(const float* __restrict__ enc,
                     const float* __restrict__ pitch,
                     const float* __restrict__ energy,
                     const float* __restrict__ pw,
                     const float* __restrict__ pb,
                     const float* __restrict__ ew,
                     const float* __restrict__ eb,
                     float* __restrict__ out)
{
    const int b   = blockIdx.y;
    const int j0  = blockIdx.x * FPB;
    const int tid = threadIdx.x;
    const int h   = tid * 4;

    // Per-thread register weights for the 4 owned channels.
    float w0[4], w1[4], w2[4], w3[4], w4[4], w5[4], cb[4];
#pragma unroll
    for (int c = 0; c < 4; c++) {
        w0[c] = __ldg(pw + (h + c) * 3 + 0);
        w1[c] = __ldg(pw + (h + c) * 3 + 1);
        w2[c] = __ldg(pw + (h + c) * 3 + 2);
        w3[c] = __ldg(ew + (h + c) * 3 + 0);
        w4[c] = __ldg(ew + (h + c) * 3 + 1);
        w5[c] = __ldg(ew + (h + c) * 3 + 2);
        cb[c] = __ldg(pb + h + c) + __ldg(eb + h + c);
    }

    __shared__ float4 sA[FPB];   // {p[-1], p[0], p[+1], idx-as-bits}
    __shared__ float4 sB[FPB];   // {e[-1], e[0], e[+1], live-as-bits}

    const int dl = g_declen[b];

    // ---- Phase 1: one frame per thread: binary search + scalar fetch ----
    {
        const int j = j0 + tid;
        int   idx = 0, live = 0;
        float pm1 = 0.f, p0 = 0.f, pp1 = 0.f;
        float em1 = 0.f, e0 = 0.f, ep1 = 0.f;
        if (j < MM) {
            const int* c = g_csum + b * TT;
            int lo = 0, hi = TT;
            while (lo < hi) {
                int mid = (lo + hi) >> 1;
                if (__ldg(c + mid) <= j) lo = mid + 1; else hi = mid;
            }
            idx  = min(lo, TT - 1);
            live = (j < dl) ? 1 : 0;
            if (live) {
                const float* P = pitch  + b * TT;
                const float* E = energy + b * TT;
                p0 = __ldg(P + idx);
                e0 = __ldg(E + idx);
                if (idx > 0)      { pm1 = __ldg(P + idx - 1); em1 = __ldg(E + idx - 1); }
                if (idx < TT - 1) { pp1 = __ldg(P + idx + 1); ep1 = __ldg(E + idx + 1); }
            }
        }
        sA[tid] = make_float4(pm1, p0, pp1, __int_as_float(idx));
        sB[tid] = make_float4(em1, e0, ep1, __int_as_float(live));
    }
    __syncthreads();

    // ---- Phase 2: all threads stream the block's frames ----
    const int nF = min(FPB, MM - j0);
    float4* __restrict__ out4 = (float4*)out;
    const float4* __restrict__ enc4 = (const float4*)enc;

    for (int f = 0; f < nF; f++) {
        const int j = j0 + f;
        const float4 a  = sA[f];
        const float4 bs = sB[f];
        const int ooff = (b * MM + j) * H4 + tid;

        if (__float_as_int(bs.w)) {
            const int idx = __float_as_int(a.w);
            const float4 e4 = __ldg(enc4 + (b * TT + idx) * H4 + tid);
            float4 r;
            r.x = e4.x + cb[0] + a.x*w0[0] + a.y*w1[0] + a.z*w2[0]
                               + bs.x*w3[0] + bs.y*w4[0] + bs.z*w5[0];
            r.y = e4.y + cb[1] + a.x*w0[1] + a.y*w1[1] + a.z*w2[1]
                               + bs.x*w3[1] + bs.y*w4[1] + bs.z*w5[1];
            r.z = e4.z + cb[2] + a.x*w0[2] + a.y*w1[2] + a.z*w2[2]
                               + bs.x*w3[2] + bs.y*w4[2] + bs.z*w5[2];
            r.w = e4.w + cb[3] + a.x*w0[3] + a.y*w1[3] + a.z*w2[3]
                               + bs.x*w3[3] + bs.y*w4[3] + bs.z*w5[3];
            out4[ooff] = r;
        } else {
            out4[ooff] = make_float4(0.f, 0.f, 0.f, 0.f);
        }
    }
}

// ---------------------------------------------------------------------------
extern "C" void kernel_launch(void* const* d_in, const int* in_sizes, int n_in,
                              void* d_out, int out_size)
{
    const float* enc    = (const float*)d_in[0];
    const float* pitch  = (const float*)d_in[1];
    const float* energy = (const float*)d_in[2];
    const float* pw     = (const float*)d_in[3];
    const float* pb     = (const float*)d_in[4];
    const float* ew     = (const float*)d_in[5];
    const float* eb     = (const float*)d_in[6];
    const int*   dur    = (const int*)d_in[7];

    float* out = (float*)d_out;

    // dec_lens tail (only if the harness allocated room for it)
    const long long main_elems = (long long)BB * MM * HH;
    float* tail = ((long long)out_size >= main_elems + BB)
                      ? out + (out_size - BB) : nullptr;

    scan_kernel<<<BB, TT>>>(dur, tail);

    dim3 grid((MM + FPB - 1) / FPB, BB);
    regulate_kernel<<<grid, FPB>>>(enc, pitch, energy, pw, pb, ew, eb, out);
}